// round 10
// baseline (speedup 1.0000x reference)
#include <cuda_runtime.h>

#define NB 32
#define NA 286
#define NAPB 288       // padded b (zero W rows 286..287)
#define CI 23
#define HH 100
#define KP 104         // padded k: 13 groups of 8 (zeros in pad)
#define NG 13
#define NSPLIT 2
#define BPW 18         // b's per warp (288 / (8 warps * 2 splits))
#define CH 6           // basis chunk per warp (3 chunks)

__device__ __align__(16) float g_W[NB * NAPB * KP];   // feat @ rW2^T, zero-padded
__device__ float g_c[NB * NA];
__device__ float g_part[NSPLIT][NB * NA];
__device__ __align__(16) float4 g_T[KP];              // per k: {c0, c1, c2, cb}

// ---------------------------------------------------------------------------
// kA: g_W rows (zero-padded), g_c, and coefficient table g_T (float4 per k).
// 288 blocks x 256 thr; block = (z = bx/9, 32 rows); warp handles 4 rows.
// ---------------------------------------------------------------------------
__global__ __launch_bounds__(256) void kA(const float* __restrict__ feat,
                                          const float* __restrict__ rW1,
                                          const float* __restrict__ rb1,
                                          const float* __restrict__ rW2,
                                          const float* __restrict__ rb2) {
    __shared__ float s_w2[HH * CI];
    __shared__ float s_f[8][4][24];
    int t = threadIdx.x, w = t >> 5, lane = t & 31;
    int bx = blockIdx.x;

    if (bx == 0 && t < KP) {             // coefficient table, k-pad zeroed
        int k = t;  bool ok = (k < HH);
        float c0 = ok ? rW1[k] : 0.f;
        float c1 = ok ? rW1[HH + k] : 0.f;
        float c2 = ok ? rW1[2 * HH + k] : 0.f;
        float cb = ok ? rb1[k] : 0.f;
        g_T[k] = make_float4(c0, c1, c2, cb);
    }

    for (int i = t; i < HH * CI; i += 256) s_w2[i] = rW2[i];

    int z = bx / 9;
    int jb = (bx % 9) * 32 + w * 4;
    for (int i = 0; i < 4; i++) {
        int j = jb + i;
        if (j < NA && lane < CI) s_f[w][i][lane] = feat[(z * NA + j) * CI + lane];
    }
    __syncthreads();

    for (int i = 0; i < 4; i++) {
        int j = jb + i;
        float* Wr = g_W + (size_t)(z * NAPB + j) * KP;
        int k0 = lane, k1 = lane + 32, k2 = lane + 64, k3 = lane + 96;
        if (j < NA) {
            float a0 = 0.f, a1 = 0.f, a2 = 0.f, a3 = 0.f;
#pragma unroll
            for (int c = 0; c < CI; c++) {
                float fv = s_f[w][i][c];
                a0 = fmaf(fv, s_w2[k0 * CI + c], a0);
                a1 = fmaf(fv, s_w2[k1 * CI + c], a1);
                a2 = fmaf(fv, s_w2[k2 * CI + c], a2);
                if (k3 < HH) a3 = fmaf(fv, s_w2[k3 * CI + c], a3);
            }
            Wr[k0] = a0;
            Wr[k1] = a1;
            Wr[k2] = a2;
            if (k3 < KP) Wr[k3] = (k3 < HH) ? a3 : 0.f;
            if (lane == 0) {
                float cc = 0.f;
#pragma unroll
                for (int c = 0; c < CI; c++) cc = fmaf(rb2[c], s_f[w][i][c], cc);
                g_c[z * NA + j] = cc;
            }
        } else {
            Wr[k0] = 0.f; Wr[k1] = 0.f; Wr[k2] = 0.f;
            if (k3 < KP) Wr[k3] = 0.f;
        }
    }
}

// ---------------------------------------------------------------------------
// kB: block = (atile, z, split); 256 thr = 32 a-lanes x 8 b-warps.
// Per k: t = xlo*cA + xhi*cB + cb (2 FMA + 2 SEL), relu via FMNMX (ALU pipe),
// acc FMA. Coeffs register-resident per 8-k group; W warp-uniform LDG.128.
// ---------------------------------------------------------------------------
__global__ __launch_bounds__(256, 3) void kB(const float* __restrict__ geom) {
    __shared__ float s_red[256];
    int t = threadIdx.x, al = t & 31, bl = t >> 5;
    int z = blockIdx.y, atile = blockIdx.x, sp = blockIdx.z;
    int a = atile * 32 + al;
    bool valid = (a < NA);
    int ca = valid ? a : (NA - 1);

    const float* gp = geom + (size_t)z * NA * 3;
    float gax = gp[ca * 3 + 0];
    float gay = gp[ca * 3 + 1];
    float gaz = gp[ca * 3 + 2];

    const float* Wz = g_W + (size_t)z * NAPB * KP;
    const float INV = 1.0f / 1.5f;
    const float PIO2 = 1.57079632679489662f;

    float acc0 = 0.f, acc1 = 0.f;
    int wbase = (sp * 8 + bl) * BPW;

    for (int cc = 0; cc < BPW; cc += CH) {
        int bb = wbase + cc;
        float xlo[CH], xhi[CH];
        bool sfl[CH];
#pragma unroll
        for (int i = 0; i < CH; i++) {
            int b = bb + i;
            int bc = (b < NA) ? b : (NA - 1);     // pad b: finite garbage, W row = 0
            float dx = gax - gp[bc * 3 + 0];
            float dy = gay - gp[bc * 3 + 1];
            float dz = gaz - gp[bc * 3 + 2];
            float d2 = fmaf(dx, dx, fmaf(dy, dy, fmaf(dz, dz, 1e-12f)));
            float r = d2 * rsqrtf(d2);
            bool s = (r >= 1.5f);
            float rr = s ? (r - 1.5f) : r;
            float q = rr * INV;
            xlo[i] = __cosf(PIO2 * fminf(q, 1.f));
            xhi[i] = __cosf(PIO2 * fminf(q - 1.f, 1.f));
            sfl[i] = s;
        }
#pragma unroll 1
        for (int g = 0; g < NG; g++) {
            float4 C[8];
#pragma unroll
            for (int k = 0; k < 8; k++) C[k] = g_T[g * 8 + k];
            const float* Wp = Wz + (size_t)bb * KP + g * 8;
#pragma unroll
            for (int i = 0; i < CH; i++) {
                const float4* wr = (const float4*)(Wp + i * KP);
                float4 w0 = wr[0];
                float4 w1 = wr[1];
                bool sb = sfl[i];
                float xl = xlo[i], xh = xhi[i];

                float cA, cB, tk;
                cA = sb ? C[0].y : C[0].x;  cB = sb ? C[0].z : C[0].y;
                tk = fmaxf(fmaf(xl, cA, fmaf(xh, cB, C[0].w)), 0.f);
                acc0 = fmaf(tk, w0.x, acc0);
                cA = sb ? C[1].y : C[1].x;  cB = sb ? C[1].z : C[1].y;
                tk = fmaxf(fmaf(xl, cA, fmaf(xh, cB, C[1].w)), 0.f);
                acc1 = fmaf(tk, w0.y, acc1);
                cA = sb ? C[2].y : C[2].x;  cB = sb ? C[2].z : C[2].y;
                tk = fmaxf(fmaf(xl, cA, fmaf(xh, cB, C[2].w)), 0.f);
                acc0 = fmaf(tk, w0.z, acc0);
                cA = sb ? C[3].y : C[3].x;  cB = sb ? C[3].z : C[3].y;
                tk = fmaxf(fmaf(xl, cA, fmaf(xh, cB, C[3].w)), 0.f);
                acc1 = fmaf(tk, w0.w, acc1);
                cA = sb ? C[4].y : C[4].x;  cB = sb ? C[4].z : C[4].y;
                tk = fmaxf(fmaf(xl, cA, fmaf(xh, cB, C[4].w)), 0.f);
                acc0 = fmaf(tk, w1.x, acc0);
                cA = sb ? C[5].y : C[5].x;  cB = sb ? C[5].z : C[5].y;
                tk = fmaxf(fmaf(xl, cA, fmaf(xh, cB, C[5].w)), 0.f);
                acc1 = fmaf(tk, w1.y, acc1);
                cA = sb ? C[6].y : C[6].x;  cB = sb ? C[6].z : C[6].y;
                tk = fmaxf(fmaf(xl, cA, fmaf(xh, cB, C[6].w)), 0.f);
                acc0 = fmaf(tk, w1.z, acc0);
                cA = sb ? C[7].y : C[7].x;  cB = sb ? C[7].z : C[7].y;
                tk = fmaxf(fmaf(xl, cA, fmaf(xh, cB, C[7].w)), 0.f);
                acc1 = fmaf(tk, w1.w, acc1);
            }
        }
    }

    s_red[t] = acc0 + acc1;
    __syncthreads();

    if (t < 32 && valid) {
        float s = 0.f;
#pragma unroll
        for (int l = 0; l < 8; l++) s += s_red[l * 32 + t];
        const float SCALE = 0.28209479177387814f / 16.911534525287763f;  // Y0/sqrt(N)
        g_part[sp][(size_t)z * NA + a] = s * SCALE;
    }
}

// ---------------------------------------------------------------------------
// kC: csum = SCALE * sum_b c[z,b]; then MLP head 286 -> 30 -> 10 -> 1
// ---------------------------------------------------------------------------
__global__ __launch_bounds__(32) void kC(const float* __restrict__ fc1W,
                                         const float* __restrict__ fc1b,
                                         const float* __restrict__ fc2W,
                                         const float* __restrict__ fc2b,
                                         const float* __restrict__ fc3W,
                                         const float* __restrict__ fc3b,
                                         float* __restrict__ out) {
    int z = blockIdx.x, t = threadIdx.x;
    __shared__ float s1[30], s2[10];

    float cs = 0.f;
    for (int i = t; i < NA; i += 32) cs += g_c[z * NA + i];
#pragma unroll
    for (int o = 16; o > 0; o >>= 1) cs += __shfl_xor_sync(0xffffffffu, cs, o);
    const float SCALE = 0.28209479177387814f / 16.911534525287763f;
    cs *= SCALE;

    const float* p0 = g_part[0] + (size_t)z * NA;
    const float* p1 = g_part[1] + (size_t)z * NA;
    if (t < 30) {
        float acc = fc1b[t];
#pragma unroll 4
        for (int i = 0; i < NA; i++)
            acc = fmaf(p0[i] + p1[i] + cs, fc1W[i * 30 + t], acc);
        s1[t] = fmaxf(acc, 0.f);
    }
    __syncthreads();
    if (t < 10) {
        float acc = fc2b[t];
#pragma unroll
        for (int i = 0; i < 30; i++)
            acc = fmaf(s1[i], fc2W[i * 10 + t], acc);
        s2[t] = fmaxf(acc, 0.f);
    }
    __syncthreads();
    if (t == 0) {
        float acc = fc3b[0];
#pragma unroll
        for (int i = 0; i < 10; i++)
            acc = fmaf(s2[i], fc3W[i], acc);
        out[z] = acc;
    }
}

// ---------------------------------------------------------------------------
extern "C" void kernel_launch(void* const* d_in, const int* in_sizes, int n_in,
                              void* d_out, int out_size) {
    const float* features = (const float*)d_in[1];
    const float* geometry = (const float*)d_in[2];
    const float* rW1  = (const float*)d_in[3];
    const float* rb1  = (const float*)d_in[4];
    const float* rW2  = (const float*)d_in[5];
    const float* rb2  = (const float*)d_in[6];
    const float* fc1W = (const float*)d_in[7];
    const float* fc1b = (const float*)d_in[8];
    const float* fc2W = (const float*)d_in[9];
    const float* fc2b = (const float*)d_in[10];
    const float* fc3W = (const float*)d_in[11];
    const float* fc3b = (const float*)d_in[12];
    float* out = (float*)d_out;

    kA<<<288, 256>>>(features, rW1, rb1, rW2, rb2);
    dim3 gB(9, NB, NSPLIT);
    kB<<<gB, 256>>>(geometry);
    kC<<<NB, 32>>>(fc1W, fc1b, fc2W, fc2b, fc3W, fc3b, out);
}

// round 12
// speedup vs baseline: 1.2660x; 1.2660x over previous
#include <cuda_runtime.h>

#define NB 32
#define NA 286
#define NAPB 288       // padded b (zero W rows 286..287)
#define CI 23
#define HH 100
#define KP 104         // padded k: 13 groups of 8 (zeros in pad)
#define NG 13
#define BPW 36         // b's per warp (288/8)
#define CH 6           // basis chunk per warp (6 chunks)

typedef unsigned long long ull;

__device__ __align__(16) float g_W[NB * NAPB * KP];  // feat@rW2^T, zero-padded
__device__ float g_c[NB * NA];
__device__ float g_part[NB * NA];
__device__ __align__(16) ull g_T[52 * 4];            // per k-pair q: {c0p,c1p,c2p,cbp}

__device__ __forceinline__ ull pk2(float x, float y) {
    ull r; asm("mov.b64 %0, {%1,%2};" : "=l"(r) : "f"(x), "f"(y)); return r;
}
__device__ __forceinline__ ull dup2(float x) {
    ull r; asm("mov.b64 %0, {%1,%1};" : "=l"(r) : "f"(x)); return r;
}
__device__ __forceinline__ void unpk2(float& x, float& y, ull v) {
    asm("mov.b64 {%0,%1}, %2;" : "=f"(x), "=f"(y) : "l"(v));
}
__device__ __forceinline__ ull fma2(ull a, ull b, ull c) {
    ull d; asm("fma.rn.f32x2 %0, %1, %2, %3;" : "=l"(d) : "l"(a), "l"(b), "l"(c)); return d;
}
// packed relu via 2 scalar FMNMX (ALU pipe); pack/unpack are reg-pair aliases
__device__ __forceinline__ ull relu2(ull v) {
    float a, b;
    asm("mov.b64 {%0,%1}, %2;" : "=f"(a), "=f"(b) : "l"(v));
    a = fmaxf(a, 0.f);
    b = fmaxf(b, 0.f);
    ull r; asm("mov.b64 %0, {%1,%2};" : "=l"(r) : "f"(a), "f"(b));
    return r;
}

// ---------------------------------------------------------------------------
// kA: g_W rows (zero-padded), g_c, packed coefficient table g_T.
// 576 blocks x 256 thr; block = (z = bx/18, 16 rows); warp handles 2 rows.
// ---------------------------------------------------------------------------
__global__ __launch_bounds__(256) void kA(const float* __restrict__ feat,
                                          const float* __restrict__ rW1,
                                          const float* __restrict__ rb1,
                                          const float* __restrict__ rW2,
                                          const float* __restrict__ rb2) {
    __shared__ float s_w2[HH * CI];
    __shared__ float s_f[8][2][24];
    int t = threadIdx.x, w = t >> 5, lane = t & 31;
    int bx = blockIdx.x;

    if (bx == 0 && t < 52) {             // packed coefficient table, k-pad zeroed
        int k = 2 * t;
        float a0 = (k < HH) ? rW1[k] : 0.f;
        float a1 = (k + 1 < HH) ? rW1[k + 1] : 0.f;
        float b0 = (k < HH) ? rW1[HH + k] : 0.f;
        float b1 = (k + 1 < HH) ? rW1[HH + k + 1] : 0.f;
        float c0 = (k < HH) ? rW1[2 * HH + k] : 0.f;
        float c1 = (k + 1 < HH) ? rW1[2 * HH + k + 1] : 0.f;
        float d0 = (k < HH) ? rb1[k] : 0.f;
        float d1 = (k + 1 < HH) ? rb1[k + 1] : 0.f;
        g_T[t * 4 + 0] = pk2(a0, a1);
        g_T[t * 4 + 1] = pk2(b0, b1);
        g_T[t * 4 + 2] = pk2(c0, c1);
        g_T[t * 4 + 3] = pk2(d0, d1);
    }

    for (int i = t; i < HH * CI; i += 256) s_w2[i] = rW2[i];

    int z = bx / 18;
    int jb = (bx % 18) * 16 + w * 2;
    for (int i = 0; i < 2; i++) {
        int j = jb + i;
        if (j < NA && lane < CI) s_f[w][i][lane] = feat[(z * NA + j) * CI + lane];
    }
    __syncthreads();

    for (int i = 0; i < 2; i++) {
        int j = jb + i;
        float* Wr = g_W + (size_t)(z * NAPB + j) * KP;
        int k0 = lane, k1 = lane + 32, k2 = lane + 64, k3 = lane + 96;
        if (j < NA) {
            float a0 = 0.f, a1 = 0.f, a2 = 0.f, a3 = 0.f;
#pragma unroll
            for (int c = 0; c < CI; c++) {
                float fv = s_f[w][i][c];
                a0 = fmaf(fv, s_w2[k0 * CI + c], a0);
                a1 = fmaf(fv, s_w2[k1 * CI + c], a1);
                a2 = fmaf(fv, s_w2[k2 * CI + c], a2);
                if (k3 < HH) a3 = fmaf(fv, s_w2[k3 * CI + c], a3);
            }
            Wr[k0] = a0;
            Wr[k1] = a1;
            Wr[k2] = a2;
            if (k3 < KP) Wr[k3] = (k3 < HH) ? a3 : 0.f;
            if (lane == 0) {
                float cc = 0.f;
#pragma unroll
                for (int c = 0; c < CI; c++) cc = fmaf(rb2[c], s_f[w][i][c], cc);
                g_c[z * NA + j] = cc;
            }
        } else {
            Wr[k0] = 0.f; Wr[k1] = 0.f; Wr[k2] = 0.f;
            if (k3 < KP) Wr[k3] = 0.f;
        }
    }
}

// ---------------------------------------------------------------------------
// kB: block = (atile, z); 256 thr = 32 a-lanes x 8 b-warps.
// Basis pre-packed per chunk (hoisted out of g-loop). Per 2k: 3 dot-fma2 +
// relu2 (2 FMNMX, ALU pipe) + acc-fma2 = 4 FMA-pipe slots.
// ---------------------------------------------------------------------------
__global__ __launch_bounds__(256, 2) void kB(const float* __restrict__ geom) {
    __shared__ float s_red[256];
    int t = threadIdx.x, al = t & 31, bl = t >> 5;
    int z = blockIdx.y, atile = blockIdx.x;
    int a = atile * 32 + al;
    bool valid = (a < NA);
    int ca = valid ? a : (NA - 1);

    const float* gp = geom + (size_t)z * NA * 3;
    float gax = gp[ca * 3 + 0];
    float gay = gp[ca * 3 + 1];
    float gaz = gp[ca * 3 + 2];

    const float* Wz = g_W + (size_t)z * NAPB * KP;
    const ulonglong2* T2 = (const ulonglong2*)g_T;

    const float INV = 1.0f / 1.5f;
    const float PIO2 = 1.57079632679489662f;

    ull acc0 = 0ull, acc1 = 0ull, acc2 = 0ull, acc3 = 0ull;

    for (int c0 = 0; c0 < BPW; c0 += CH) {
        int bb = bl * BPW + c0;
        ull x0p[CH], x1p[CH], x2p[CH];    // packed basis, live across g-loop
#pragma unroll
        for (int i = 0; i < CH; i++) {
            int b = bb + i;
            int bc = (b < NA) ? b : (NA - 1);   // pad b: finite garbage, W row = 0
            float dx = gax - gp[bc * 3 + 0];
            float dy = gay - gp[bc * 3 + 1];
            float dz = gaz - gp[bc * 3 + 2];
            float d2 = fmaf(dx, dx, fmaf(dy, dy, fmaf(dz, dz, 1e-12f)));
            float r = d2 * rsqrtf(d2);
            bool s = (r >= 1.5f);
            float rr = s ? (r - 1.5f) : r;
            float ulo = __cosf(PIO2 * fminf(rr * INV, 1.f));
            float uhi = __cosf(PIO2 * fminf(rr * INV - 1.f, 1.f));
            x0p[i] = dup2(s ? 0.f : ulo);
            x1p[i] = dup2(s ? ulo : uhi);
            x2p[i] = dup2(s ? uhi : 0.f);
        }
#pragma unroll 1
        for (int g = 0; g < NG; g++) {
            ulonglong2 A0 = T2[g * 8 + 0], B0 = T2[g * 8 + 1];
            ulonglong2 A1 = T2[g * 8 + 2], B1 = T2[g * 8 + 3];
            ulonglong2 A2 = T2[g * 8 + 4], B2 = T2[g * 8 + 5];
            ulonglong2 A3 = T2[g * 8 + 6], B3 = T2[g * 8 + 7];
            const float* Wp = Wz + (size_t)bb * KP + g * 8;
#pragma unroll
            for (int i = 0; i < CH; i++) {
                const ulonglong2* wr = (const ulonglong2*)(Wp + i * KP);
                ulonglong2 wlo = wr[0];   // k-pairs 0,1 of this group
                ulonglong2 whi = wr[1];   // k-pairs 2,3

                ull t0 = fma2(x0p[i], A0.x, fma2(x1p[i], A0.y, fma2(x2p[i], B0.x, B0.y)));
                acc0 = fma2(relu2(t0), wlo.x, acc0);

                ull t1 = fma2(x0p[i], A1.x, fma2(x1p[i], A1.y, fma2(x2p[i], B1.x, B1.y)));
                acc1 = fma2(relu2(t1), wlo.y, acc1);

                ull t2 = fma2(x0p[i], A2.x, fma2(x1p[i], A2.y, fma2(x2p[i], B2.x, B2.y)));
                acc2 = fma2(relu2(t2), whi.x, acc2);

                ull t3 = fma2(x0p[i], A3.x, fma2(x1p[i], A3.y, fma2(x2p[i], B3.x, B3.y)));
                acc3 = fma2(relu2(t3), whi.y, acc3);
            }
        }
    }

    float p0, p1, q0, q1, r0, r1, s0, s1;
    unpk2(p0, p1, acc0);
    unpk2(q0, q1, acc1);
    unpk2(r0, r1, acc2);
    unpk2(s0, s1, acc3);
    s_red[t] = ((p0 + p1) + (q0 + q1)) + ((r0 + r1) + (s0 + s1));
    __syncthreads();

    if (t < 32 && valid) {
        float s = 0.f;
#pragma unroll
        for (int l = 0; l < 8; l++) s += s_red[l * 32 + t];
        const float SCALE = 0.28209479177387814f / 16.911534525287763f;  // Y0/sqrt(N)
        g_part[(size_t)z * NA + a] = s * SCALE;
    }
}

// ---------------------------------------------------------------------------
// kC: csum = SCALE * sum_b c[z,b]; then MLP head 286 -> 30 -> 10 -> 1
// ---------------------------------------------------------------------------
__global__ __launch_bounds__(32) void kC(const float* __restrict__ fc1W,
                                         const float* __restrict__ fc1b,
                                         const float* __restrict__ fc2W,
                                         const float* __restrict__ fc2b,
                                         const float* __restrict__ fc3W,
                                         const float* __restrict__ fc3b,
                                         float* __restrict__ out) {
    int z = blockIdx.x, t = threadIdx.x;
    __shared__ float s1[30], s2[10];

    float cs = 0.f;
    for (int i = t; i < NA; i += 32) cs += g_c[z * NA + i];
#pragma unroll
    for (int o = 16; o > 0; o >>= 1) cs += __shfl_xor_sync(0xffffffffu, cs, o);
    const float SCALE = 0.28209479177387814f / 16.911534525287763f;
    cs *= SCALE;

    const float* p = g_part + (size_t)z * NA;
    if (t < 30) {
        float acc = fc1b[t];
#pragma unroll 4
        for (int i = 0; i < NA; i++)
            acc = fmaf(p[i] + cs, fc1W[i * 30 + t], acc);
        s1[t] = fmaxf(acc, 0.f);
    }
    __syncthreads();
    if (t < 10) {
        float acc = fc2b[t];
#pragma unroll
        for (int i = 0; i < 30; i++)
            acc = fmaf(s1[i], fc2W[i * 10 + t], acc);
        s2[t] = fmaxf(acc, 0.f);
    }
    __syncthreads();
    if (t == 0) {
        float acc = fc3b[0];
#pragma unroll
        for (int i = 0; i < 10; i++)
            acc = fmaf(s2[i], fc3W[i], acc);
        out[z] = acc;
    }
}

// ---------------------------------------------------------------------------
extern "C" void kernel_launch(void* const* d_in, const int* in_sizes, int n_in,
                              void* d_out, int out_size) {
    const float* features = (const float*)d_in[1];
    const float* geometry = (const float*)d_in[2];
    const float* rW1  = (const float*)d_in[3];
    const float* rb1  = (const float*)d_in[4];
    const float* rW2  = (const float*)d_in[5];
    const float* rb2  = (const float*)d_in[6];
    const float* fc1W = (const float*)d_in[7];
    const float* fc1b = (const float*)d_in[8];
    const float* fc2W = (const float*)d_in[9];
    const float* fc2b = (const float*)d_in[10];
    const float* fc3W = (const float*)d_in[11];
    const float* fc3b = (const float*)d_in[12];
    float* out = (float*)d_out;

    kA<<<576, 256>>>(features, rW1, rb1, rW2, rb2);
    dim3 gB(9, NB);
    kB<<<gB, 256>>>(geometry);
    kC<<<NB, 32>>>(fc1W, fc1b, fc2W, fc2b, fc3W, fc3b, out);
}